// round 3
// baseline (speedup 1.0000x reference)
#include <cuda_runtime.h>
#include <cstdint>

#define NN_MAX 60000
#define EE_MAX 960000

__device__ float g_asrc[NN_MAX * 64];
__device__ float g_adst[NN_MAX * 64];
__device__ float g_v[NN_MAX * 64];
__device__ float g_nd[NN_MAX * 128];   // [node][0:64]=num, [64:128]=den

typedef unsigned long long u64;

__device__ __forceinline__ u64 pack2(float a, float b) {
    u64 r; asm("mov.b64 %0, {%1, %2};" : "=l"(r) : "f"(a), "f"(b)); return r;
}
__device__ __forceinline__ void unpack2(u64 v, float& a, float& b) {
    asm("mov.b64 {%0, %1}, %2;" : "=f"(a), "=f"(b) : "l"(v));
}
__device__ __forceinline__ u64 ffma2(u64 a, u64 b, u64 c) {
    u64 r; asm("fma.rn.f32x2 %0, %1, %2, %3;" : "=l"(r) : "l"(a), "l"(b), "l"(c)); return r;
}
__device__ __forceinline__ void red_v4(float* p, float a, float b, float c, float d) {
    asm volatile("red.global.add.v4.f32 [%0], {%1,%2,%3,%4};"
                 :: "l"(p), "f"(a), "f"(b), "f"(c), "f"(d) : "memory");
}

// ================= node kernel =================
struct NodeSmem {
    float Win[4096], Ws[4096], Wd[4096], Wl[4096];
    float bin[64], bl[64];
    u64 xd[8][64];
    u64 hd[8][64];
};

__global__ __launch_bounds__(256, 3) void node_kernel(
    const float* __restrict__ x,
    const float* __restrict__ Win, const float* __restrict__ bin,
    const float* __restrict__ Wsrc, const float* __restrict__ Wdst,
    const float* __restrict__ Wlin, const float* __restrict__ blin, int nn)
{
    extern __shared__ char raw[];
    NodeSmem& s = *reinterpret_cast<NodeSmem*>(raw);
    int tid = threadIdx.x;
    for (int i = tid; i < 4096; i += 256) {
        s.Win[i] = Win[i]; s.Ws[i] = Wsrc[i]; s.Wd[i] = Wdst[i]; s.Wl[i] = Wlin[i];
    }
    if (tid < 64) { s.bin[tid] = bin[tid]; s.bl[tid] = blin[tid]; }
    __syncthreads();

    int warp = tid >> 5, lane = tid & 31, c0 = lane * 2;
    u64 binp = *reinterpret_cast<const u64*>(&s.bin[c0]);
    u64 blp  = *reinterpret_cast<const u64*>(&s.bl[c0]);
    int totW = (gridDim.x * 256) >> 5;

    for (int node = (blockIdx.x * 256 + tid) >> 5; node < nn; node += totW) {
        float2 xv = *reinterpret_cast<const float2*>(&x[node * 64 + c0]);
        {
            ulonglong2 t; t.x = pack2(xv.x, xv.x); t.y = pack2(xv.y, xv.y);
            *reinterpret_cast<ulonglong2*>(&s.xd[warp][c0]) = t;
        }
        __syncwarp();
        u64 acc = binp;
        #pragma unroll 8
        for (int k = 0; k < 64; k += 2) {
            ulonglong2 x2 = *reinterpret_cast<const ulonglong2*>(&s.xd[warp][k]);
            u64 w0 = *reinterpret_cast<const u64*>(&s.Win[k * 64 + c0]);
            u64 w1 = *reinterpret_cast<const u64*>(&s.Win[(k + 1) * 64 + c0]);
            acc = ffma2(x2.x, w0, acc);
            acc = ffma2(x2.y, w1, acc);
        }
        float h0, h1; unpack2(acc, h0, h1);
        h0 = fmaxf(h0, 0.f); h1 = fmaxf(h1, 0.f);
        __syncwarp();
        {
            ulonglong2 t; t.x = pack2(h0, h0); t.y = pack2(h1, h1);
            *reinterpret_cast<ulonglong2*>(&s.hd[warp][c0]) = t;
        }
        __syncwarp();
        u64 as = 0ull, ad = 0ull, av = blp;
        #pragma unroll 8
        for (int k = 0; k < 64; k += 2) {
            ulonglong2 h2 = *reinterpret_cast<const ulonglong2*>(&s.hd[warp][k]);
            u64 ws0 = *reinterpret_cast<const u64*>(&s.Ws[k * 64 + c0]);
            u64 wd0 = *reinterpret_cast<const u64*>(&s.Wd[k * 64 + c0]);
            u64 wl0 = *reinterpret_cast<const u64*>(&s.Wl[k * 64 + c0]);
            as = ffma2(h2.x, ws0, as); ad = ffma2(h2.x, wd0, ad); av = ffma2(h2.x, wl0, av);
            u64 ws1 = *reinterpret_cast<const u64*>(&s.Ws[(k + 1) * 64 + c0]);
            u64 wd1 = *reinterpret_cast<const u64*>(&s.Wd[(k + 1) * 64 + c0]);
            u64 wl1 = *reinterpret_cast<const u64*>(&s.Wl[(k + 1) * 64 + c0]);
            as = ffma2(h2.y, ws1, as); ad = ffma2(h2.y, wd1, ad); av = ffma2(h2.y, wl1, av);
        }
        float o0, o1;
        unpack2(as, o0, o1); *reinterpret_cast<float2*>(&g_asrc[node * 64 + c0]) = make_float2(o0, o1);
        unpack2(ad, o0, o1); *reinterpret_cast<float2*>(&g_adst[node * 64 + c0]) = make_float2(o0, o1);
        unpack2(av, o0, o1); *reinterpret_cast<float2*>(&g_v[node * 64 + c0])    = make_float2(o0, o1);
        *reinterpret_cast<float4*>(&g_nd[node * 128 + lane * 4]) = make_float4(0.f, 0.f, 0.f, 0.f);
        __syncwarp();
    }
}

// ================= edge kernel =================
#define NWARP 8
#define ME 8

struct __align__(16) EdgeSmem {
    float Wp2[4096], Wa1[4096], Wa2[4096];   // row-major [k][n]
    float Wp1[192];                           // [k][n], k=0..2
    float bp1[64], bp2[64], ba1[64], ba2[64];
    float padA[64];                           // keep Xd 16B-aligned region tidy
    u64 Xd[NWARP][ME][64];                    // duplicated activations
    float D[NWARP][ME][64];                   // delta
    int srcs[NWARP][ME], dsts[NWARP][ME];
    float pd[NWARP][ME][3];
};

__global__ __launch_bounds__(256, 2) void edge_kernel(
    const float* __restrict__ pos, const int* __restrict__ ei,
    const float* __restrict__ Wp1, const float* __restrict__ bp1,
    const float* __restrict__ Wp2, const float* __restrict__ bp2,
    const float* __restrict__ Wa1, const float* __restrict__ ba1,
    const float* __restrict__ Wa2, const float* __restrict__ ba2, int ne)
{
    extern __shared__ char raw[];
    EdgeSmem& s = *reinterpret_cast<EdgeSmem*>(raw);
    int tid = threadIdx.x;
    for (int i = tid; i < 4096; i += 256) {
        s.Wp2[i] = Wp2[i]; s.Wa1[i] = Wa1[i]; s.Wa2[i] = Wa2[i];
    }
    for (int i = tid; i < 192; i += 256) s.Wp1[i] = Wp1[i];
    if (tid < 64) { s.bp1[tid] = bp1[tid]; s.bp2[tid] = bp2[tid]; s.ba1[tid] = ba1[tid]; s.ba2[tid] = ba2[tid]; }
    __syncthreads();

    int warp = tid >> 5, lane = tid & 31, c0 = lane * 2;
    bool even = (lane & 1) == 0;
    u64 b1p = *reinterpret_cast<const u64*>(&s.bp1[c0]);
    u64 b2p = *reinterpret_cast<const u64*>(&s.bp2[c0]);
    u64 b3p = *reinterpret_cast<const u64*>(&s.ba1[c0]);
    u64 b4p = *reinterpret_cast<const u64*>(&s.ba2[c0]);
    u64 wp0 = *reinterpret_cast<const u64*>(&s.Wp1[c0]);
    u64 wp1 = *reinterpret_cast<const u64*>(&s.Wp1[64 + c0]);
    u64 wp2 = *reinterpret_cast<const u64*>(&s.Wp1[128 + c0]);

    int gw = blockIdx.x * NWARP + warp;
    int totW = gridDim.x * NWARP;
    int ngroups = (ne + ME - 1) / ME;

    for (int g = gw; g < ngroups; g += totW) {
        int e0 = g * ME;
        if (lane < ME) {
            int eidx = e0 + lane;
            int si = 0, di = 0;
            float p0 = 0.f, p1 = 0.f, p2 = 0.f;
            if (eidx < ne) {
                si = ei[eidx];
                di = ei[ne + eidx];
                p0 = pos[di * 3 + 0] - pos[si * 3 + 0];
                p1 = pos[di * 3 + 1] - pos[si * 3 + 1];
                p2 = pos[di * 3 + 2] - pos[si * 3 + 2];
            }
            s.srcs[warp][lane] = si; s.dsts[warp][lane] = di;
            s.pd[warp][lane][0] = p0; s.pd[warp][lane][1] = p1; s.pd[warp][lane][2] = p2;
        }
        __syncwarp();

        // ---- h1 = relu(pd @ Wp1 + bp1) -> Xd (duplicated) ----
        #pragma unroll
        for (int e = 0; e < ME; e++) {
            float p0 = s.pd[warp][e][0], p1 = s.pd[warp][e][1], p2 = s.pd[warp][e][2];
            u64 acc = b1p;
            acc = ffma2(pack2(p0, p0), wp0, acc);
            acc = ffma2(pack2(p1, p1), wp1, acc);
            acc = ffma2(pack2(p2, p2), wp2, acc);
            float a0, a1; unpack2(acc, a0, a1);
            a0 = fmaxf(a0, 0.f); a1 = fmaxf(a1, 0.f);
            ulonglong2 t; t.x = pack2(a0, a0); t.y = pack2(a1, a1);
            *reinterpret_cast<ulonglong2*>(&s.Xd[warp][e][c0]) = t;
        }
        // prefetch a_dst[dst], a_src[src]
        float2 ad[ME], asr[ME];
        #pragma unroll
        for (int e = 0; e < ME; e++) {
            int si = s.srcs[warp][e], di = s.dsts[warp][e];
            ad[e]  = *reinterpret_cast<const float2*>(&g_adst[di * 64 + c0]);
            asr[e] = *reinterpret_cast<const float2*>(&g_asrc[si * 64 + c0]);
        }
        __syncwarp();

        // ---- delta = relu(h1 @ Wp2 + bp2) ----
        u64 acc[ME];
        #pragma unroll
        for (int e = 0; e < ME; e++) acc[e] = b2p;
        #pragma unroll 8
        for (int k = 0; k < 64; k += 2) {
            u64 w0 = *reinterpret_cast<const u64*>(&s.Wp2[k * 64 + c0]);
            u64 w1 = *reinterpret_cast<const u64*>(&s.Wp2[(k + 1) * 64 + c0]);
            #pragma unroll
            for (int e = 0; e < ME; e++) {
                ulonglong2 x2 = *reinterpret_cast<const ulonglong2*>(&s.Xd[warp][e][k]);
                acc[e] = ffma2(x2.x, w0, acc[e]);
                acc[e] = ffma2(x2.y, w1, acc[e]);
            }
        }
        __syncwarp();
        #pragma unroll
        for (int e = 0; e < ME; e++) {
            float d0, d1; unpack2(acc[e], d0, d1);
            d0 = fmaxf(d0, 0.f); d1 = fmaxf(d1, 0.f);
            *reinterpret_cast<float2*>(&s.D[warp][e][c0]) = make_float2(d0, d1);
            float q0 = ad[e].x - asr[e].x + d0;
            float q1 = ad[e].y - asr[e].y + d1;
            ulonglong2 t; t.x = pack2(q0, q0); t.y = pack2(q1, q1);
            *reinterpret_cast<ulonglong2*>(&s.Xd[warp][e][c0]) = t;
        }
        __syncwarp();

        // ---- t = relu(q @ Wa1 + ba1) ----
        #pragma unroll
        for (int e = 0; e < ME; e++) acc[e] = b3p;
        #pragma unroll 8
        for (int k = 0; k < 64; k += 2) {
            u64 w0 = *reinterpret_cast<const u64*>(&s.Wa1[k * 64 + c0]);
            u64 w1 = *reinterpret_cast<const u64*>(&s.Wa1[(k + 1) * 64 + c0]);
            #pragma unroll
            for (int e = 0; e < ME; e++) {
                ulonglong2 x2 = *reinterpret_cast<const ulonglong2*>(&s.Xd[warp][e][k]);
                acc[e] = ffma2(x2.x, w0, acc[e]);
                acc[e] = ffma2(x2.y, w1, acc[e]);
            }
        }
        __syncwarp();
        #pragma unroll
        for (int e = 0; e < ME; e++) {
            float t0, t1; unpack2(acc[e], t0, t1);
            t0 = fmaxf(t0, 0.f); t1 = fmaxf(t1, 0.f);
            ulonglong2 t; t.x = pack2(t0, t0); t.y = pack2(t1, t1);
            *reinterpret_cast<ulonglong2*>(&s.Xd[warp][e][c0]) = t;
        }
        __syncwarp();

        // prefetch v[src]
        float2 vv[ME];
        #pragma unroll
        for (int e = 0; e < ME; e++)
            vv[e] = *reinterpret_cast<const float2*>(&g_v[s.srcs[warp][e] * 64 + c0]);

        // ---- a = relu(t @ Wa2 + ba2); p = exp(a); vectorized RED ----
        #pragma unroll
        for (int e = 0; e < ME; e++) acc[e] = b4p;
        #pragma unroll 8
        for (int k = 0; k < 64; k += 2) {
            u64 w0 = *reinterpret_cast<const u64*>(&s.Wa2[k * 64 + c0]);
            u64 w1 = *reinterpret_cast<const u64*>(&s.Wa2[(k + 1) * 64 + c0]);
            #pragma unroll
            for (int e = 0; e < ME; e++) {
                ulonglong2 x2 = *reinterpret_cast<const ulonglong2*>(&s.Xd[warp][e][k]);
                acc[e] = ffma2(x2.x, w0, acc[e]);
                acc[e] = ffma2(x2.y, w1, acc[e]);
            }
        }
        #pragma unroll
        for (int e = 0; e < ME; e++) {
            if (e0 + e < ne) {   // warp-uniform guard
                float a0, a1; unpack2(acc[e], a0, a1);
                float p0 = __expf(fmaxf(a0, 0.f));
                float p1 = __expf(fmaxf(a1, 0.f));
                float2 dd = *reinterpret_cast<const float2*>(&s.D[warp][e][c0]);
                float num0 = p0 * (vv[e].x + dd.x);
                float num1 = p1 * (vv[e].y + dd.y);
                // lane-pair exchange: even lanes emit numerator v4, odd lanes denominator v4
                float sa = even ? p0 : num0;
                float sb = even ? p1 : num1;
                float ra = __shfl_xor_sync(0xffffffffu, sa, 1);
                float rb = __shfl_xor_sync(0xffffffffu, sb, 1);
                float* nd = &g_nd[s.dsts[warp][e] * 128];
                if (even) red_v4(&nd[c0], num0, num1, ra, rb);
                else      red_v4(&nd[64 + c0 - 2], ra, rb, p0, p1);
            }
        }
        __syncwarp();
    }
}

// ================= out kernel =================
struct OutSmem {
    float W[4096];
    float b[64];
    u64 rd[8][64];
};

__global__ __launch_bounds__(256, 3) void out_kernel(
    const float* __restrict__ Wout, const float* __restrict__ bout,
    float* __restrict__ out, int nn)
{
    extern __shared__ char raw[];
    OutSmem& s = *reinterpret_cast<OutSmem*>(raw);
    int tid = threadIdx.x;
    for (int i = tid; i < 4096; i += 256) s.W[i] = Wout[i];
    if (tid < 64) s.b[tid] = bout[tid];
    __syncthreads();

    int warp = tid >> 5, lane = tid & 31, c0 = lane * 2;
    u64 bp = *reinterpret_cast<const u64*>(&s.b[c0]);
    int totW = (gridDim.x * 256) >> 5;
    for (int node = (blockIdx.x * 256 + tid) >> 5; node < nn; node += totW) {
        float2 nm = *reinterpret_cast<float2*>(&g_nd[node * 128 + c0]);
        float2 dn = *reinterpret_cast<float2*>(&g_nd[node * 128 + 64 + c0]);
        float r0 = nm.x / (dn.x + 1e-16f);
        float r1 = nm.y / (dn.y + 1e-16f);
        {
            ulonglong2 t; t.x = pack2(r0, r0); t.y = pack2(r1, r1);
            *reinterpret_cast<ulonglong2*>(&s.rd[warp][c0]) = t;
        }
        __syncwarp();
        u64 acc = bp;
        #pragma unroll 8
        for (int k = 0; k < 64; k += 2) {
            ulonglong2 x2 = *reinterpret_cast<const ulonglong2*>(&s.rd[warp][k]);
            u64 w0 = *reinterpret_cast<const u64*>(&s.W[k * 64 + c0]);
            u64 w1 = *reinterpret_cast<const u64*>(&s.W[(k + 1) * 64 + c0]);
            acc = ffma2(x2.x, w0, acc);
            acc = ffma2(x2.y, w1, acc);
        }
        float o0, o1; unpack2(acc, o0, o1);
        *reinterpret_cast<float2*>(&out[node * 64 + c0]) =
            make_float2(fmaxf(o0, 0.f), fmaxf(o1, 0.f));
        __syncwarp();
    }
}

// ================= launch =================
extern "C" void kernel_launch(void* const* d_in, const int* in_sizes, int n_in,
                              void* d_out, int out_size)
{
    const float* x     = (const float*)d_in[0];
    const float* pos   = (const float*)d_in[1];
    const float* W_in  = (const float*)d_in[2];
    const float* b_in  = (const float*)d_in[3];
    const float* W_src = (const float*)d_in[4];
    const float* W_dst = (const float*)d_in[5];
    const float* W_lin = (const float*)d_in[6];
    const float* b_lin = (const float*)d_in[7];
    const float* Wp1   = (const float*)d_in[8];
    const float* bp1   = (const float*)d_in[9];
    const float* Wp2   = (const float*)d_in[10];
    const float* bp2   = (const float*)d_in[11];
    const float* Wa1   = (const float*)d_in[12];
    const float* ba1   = (const float*)d_in[13];
    const float* Wa2   = (const float*)d_in[14];
    const float* ba2   = (const float*)d_in[15];
    const float* W_out = (const float*)d_in[16];
    const float* b_out = (const float*)d_in[17];
    const int*   ei    = (const int*)d_in[18];
    float* out = (float*)d_out;

    int nn = in_sizes[0] / 64;
    int ne = in_sizes[18] / 2;

    cudaFuncSetAttribute(node_kernel, cudaFuncAttributeMaxDynamicSharedMemorySize, (int)sizeof(NodeSmem));
    cudaFuncSetAttribute(edge_kernel, cudaFuncAttributeMaxDynamicSharedMemorySize, (int)sizeof(EdgeSmem));
    cudaFuncSetAttribute(out_kernel,  cudaFuncAttributeMaxDynamicSharedMemorySize, (int)sizeof(OutSmem));

    node_kernel<<<592, 256, sizeof(NodeSmem)>>>(x, W_in, b_in, W_src, W_dst, W_lin, b_lin, nn);
    edge_kernel<<<592, 256, sizeof(EdgeSmem)>>>(pos, ei, Wp1, bp1, Wp2, bp2, Wa1, ba1, Wa2, ba2, ne);
    out_kernel<<<592, 256, sizeof(OutSmem)>>>(W_out, b_out, out, nn);
}

// round 7
// speedup vs baseline: 1.6587x; 1.6587x over previous
#include <cuda_runtime.h>
#include <cstdint>

#define NN_MAX 60000
#define EE_MAX 960000

__device__ float g_asrc[NN_MAX * 64];
__device__ float g_adst[NN_MAX * 64];
__device__ float g_v[NN_MAX * 64];
__device__ float g_nd[NN_MAX * 128];   // [node][0:64]=num, [64:128]=den

// ---------------- helpers ----------------
__device__ __forceinline__ float ttf(float x) {   // round-to-nearest tf32 (b32 dst!)
    uint32_t r; asm("cvt.rna.tf32.f32 %0, %1;" : "=r"(r) : "f"(x));
    return __uint_as_float(r);
}
__device__ __forceinline__ void red_v4(float* p, float a, float b, float c, float d) {
    asm volatile("red.global.add.v4.f32 [%0], {%1,%2,%3,%4};"
                 :: "l"(p), "f"(a), "f"(b), "f"(c), "f"(d) : "memory");
}
// exp(a) for a >= 0 on the FMA pipe (no MUFU): 2^t, t = a*log2e
__device__ __forceinline__ float fexp(float a) {
    float t = a * 1.4426950408889634f;
    float fi = rintf(t);
    float f = t - fi;
    float p = fmaf(f, 1.3333558e-3f, 9.6181291e-3f);
    p = fmaf(p, f, 5.5504109e-2f);
    p = fmaf(p, f, 2.4022651e-1f);
    p = fmaf(p, f, 6.9314718e-1f);
    p = fmaf(p, f, 1.0f);
    return p * __int_as_float(((int)fi + 127) << 23);
}
__device__ __forceinline__ void mma_tf32(float* d, uint32_t a0, uint32_t a1,
                                         uint32_t a2, uint32_t a3,
                                         uint32_t b0, uint32_t b1) {
    asm volatile(
        "mma.sync.aligned.m16n8k8.row.col.f32.tf32.tf32.f32 "
        "{%0,%1,%2,%3}, {%4,%5,%6,%7}, {%8,%9}, {%0,%1,%2,%3};"
        : "+f"(d[0]), "+f"(d[1]), "+f"(d[2]), "+f"(d[3])
        : "r"(a0), "r"(a1), "r"(a2), "r"(a3), "r"(b0), "r"(b1));
}

// ================= node kernel (round-1 version) =================
struct NodeSmem {
    float Win[4096], Ws[4096], Wd[4096], Wl[4096];
    float bin[64], bl[64];
    float xs[8][64];
    float hs[8][64];
};

__global__ __launch_bounds__(256, 3) void node_kernel(
    const float* __restrict__ x,
    const float* __restrict__ Win, const float* __restrict__ bin,
    const float* __restrict__ Wsrc, const float* __restrict__ Wdst,
    const float* __restrict__ Wlin, const float* __restrict__ blin, int nn)
{
    extern __shared__ char raw[];
    NodeSmem& s = *reinterpret_cast<NodeSmem*>(raw);
    int tid = threadIdx.x;
    for (int i = tid; i < 4096; i += 256) {
        s.Win[i] = Win[i]; s.Ws[i] = Wsrc[i]; s.Wd[i] = Wdst[i]; s.Wl[i] = Wlin[i];
    }
    if (tid < 64) { s.bin[tid] = bin[tid]; s.bl[tid] = blin[tid]; }
    __syncthreads();

    int warp = tid >> 5, lane = tid & 31, c0 = lane * 2;
    int totW = (gridDim.x * 256) >> 5;
    for (int node = (blockIdx.x * 256 + tid) >> 5; node < nn; node += totW) {
        float2 xv = *reinterpret_cast<const float2*>(&x[node * 64 + c0]);
        s.xs[warp][c0] = xv.x; s.xs[warp][c0 + 1] = xv.y;
        __syncwarp();
        float h0 = s.bin[c0], h1 = s.bin[c0 + 1];
        #pragma unroll 16
        for (int k = 0; k < 64; k++) {
            float xk = s.xs[warp][k];
            float2 w = *reinterpret_cast<float2*>(&s.Win[k * 64 + c0]);
            h0 = fmaf(xk, w.x, h0); h1 = fmaf(xk, w.y, h1);
        }
        h0 = fmaxf(h0, 0.f); h1 = fmaxf(h1, 0.f);
        __syncwarp();
        s.hs[warp][c0] = h0; s.hs[warp][c0 + 1] = h1;
        __syncwarp();
        float s0 = 0.f, s1 = 0.f, d0 = 0.f, d1 = 0.f;
        float v0 = s.bl[c0], v1 = s.bl[c0 + 1];
        #pragma unroll 16
        for (int k = 0; k < 64; k++) {
            float hk = s.hs[warp][k];
            float2 ws = *reinterpret_cast<float2*>(&s.Ws[k * 64 + c0]);
            float2 wd = *reinterpret_cast<float2*>(&s.Wd[k * 64 + c0]);
            float2 wl = *reinterpret_cast<float2*>(&s.Wl[k * 64 + c0]);
            s0 = fmaf(hk, ws.x, s0); s1 = fmaf(hk, ws.y, s1);
            d0 = fmaf(hk, wd.x, d0); d1 = fmaf(hk, wd.y, d1);
            v0 = fmaf(hk, wl.x, v0); v1 = fmaf(hk, wl.y, v1);
        }
        *reinterpret_cast<float2*>(&g_asrc[node * 64 + c0]) = make_float2(s0, s1);
        *reinterpret_cast<float2*>(&g_adst[node * 64 + c0]) = make_float2(d0, d1);
        *reinterpret_cast<float2*>(&g_v[node * 64 + c0])    = make_float2(v0, v1);
        *reinterpret_cast<float4*>(&g_nd[node * 128 + lane * 4]) = make_float4(0.f, 0.f, 0.f, 0.f);
        __syncwarp();
    }
}

// ================= edge kernel: mma.sync tf32 =================
// Tile = 256 edges, 16 warps (each warp owns 16 edge-rows).
// Weights in smem [k][n] stride 72 (B-frag conflict-free);
// activations [row][col] stride 68 (A-frag conflict-free).
struct ESmem {
    float W2[64 * 72], W3[64 * 72], W4[64 * 72];
    float A[256 * 68];
    float Dl[256 * 68];
    float Wp1[192], b1[64], b2[64], b3[64], b4[64];
    float px[256], py[256], pz[256];
    int si[256], di[256];
};

__device__ __forceinline__ void gemm16(const float* As, const float* Ws,
                                       int warp, int lane, float acc[8][4]) {
    const uint32_t* Aw = reinterpret_cast<const uint32_t*>(As);
    const uint32_t* Bw = reinterpret_cast<const uint32_t*>(Ws);
    int base0 = (warp * 16 + (lane >> 2)) * 68 + (lane & 3);
    #pragma unroll
    for (int k8 = 0; k8 < 8; k8++) {
        uint32_t a0 = Aw[base0 + k8 * 8];
        uint32_t a1 = Aw[base0 + 8 * 68 + k8 * 8];
        uint32_t a2 = Aw[base0 + k8 * 8 + 4];
        uint32_t a3 = Aw[base0 + 8 * 68 + k8 * 8 + 4];
        int bb = (k8 * 8 + (lane & 3)) * 72 + (lane >> 2);
        #pragma unroll
        for (int n = 0; n < 8; n++) {
            mma_tf32(acc[n], a0, a1, a2, a3, Bw[bb + n * 8], Bw[bb + 288 + n * 8]);
        }
    }
}

__global__ __launch_bounds__(512, 1) void edge_mma_kernel(
    const float* __restrict__ pos, const int* __restrict__ ei,
    const float* __restrict__ Wp1, const float* __restrict__ bp1,
    const float* __restrict__ Wp2, const float* __restrict__ bp2,
    const float* __restrict__ Wa1, const float* __restrict__ ba1,
    const float* __restrict__ Wa2, const float* __restrict__ ba2, int ne)
{
    extern __shared__ char raw[];
    ESmem& s = *reinterpret_cast<ESmem*>(raw);
    int tid = threadIdx.x;

    for (int i = tid; i < 4096; i += 512) {
        int k = i >> 6, n = i & 63;
        s.W2[k * 72 + n] = ttf(Wp2[i]);
        s.W3[k * 72 + n] = ttf(Wa1[i]);
        s.W4[k * 72 + n] = ttf(Wa2[i]);
    }
    if (tid < 192) s.Wp1[tid] = Wp1[tid];
    if (tid < 64) { s.b1[tid] = bp1[tid]; s.b2[tid] = bp2[tid]; s.b3[tid] = ba1[tid]; s.b4[tid] = ba2[tid]; }
    __syncthreads();

    int warp = tid >> 5, lane = tid & 31;
    int ntiles = (ne + 255) / 256;

    for (int tile = blockIdx.x; tile < ntiles; tile += gridDim.x) {
        __syncthreads();
        if (tid < 256) {
            int ed = tile * 256 + tid;
            int si = 0, di = 0;
            float p0 = 0.f, p1 = 0.f, p2 = 0.f;
            if (ed < ne) {
                si = ei[ed]; di = ei[ne + ed];
                p0 = pos[di * 3 + 0] - pos[si * 3 + 0];
                p1 = pos[di * 3 + 1] - pos[si * 3 + 1];
                p2 = pos[di * 3 + 2] - pos[si * 3 + 2];
            }
            s.si[tid] = si; s.di[tid] = di;
            s.px[tid] = p0; s.py[tid] = p1; s.pz[tid] = p2;
        }
        __syncthreads();

        // ---- stage0: h1 = relu(pd @ Wp1 + b1) -> A (tf32) ----
        {
            int row = warp * 16 + (lane >> 1);
            int ch = (lane & 1) * 32;
            float p0 = s.px[row], p1 = s.py[row], p2 = s.pz[row];
            #pragma unroll
            for (int j = 0; j < 8; j++) {
                int c = ch + j * 4;
                float4 w0 = *reinterpret_cast<const float4*>(&s.Wp1[c]);
                float4 w1 = *reinterpret_cast<const float4*>(&s.Wp1[64 + c]);
                float4 w2 = *reinterpret_cast<const float4*>(&s.Wp1[128 + c]);
                float4 bb = *reinterpret_cast<const float4*>(&s.b1[c]);
                float4 o;
                o.x = ttf(fmaxf(fmaf(p2, w2.x, fmaf(p1, w1.x, fmaf(p0, w0.x, bb.x))), 0.f));
                o.y = ttf(fmaxf(fmaf(p2, w2.y, fmaf(p1, w1.y, fmaf(p0, w0.y, bb.y))), 0.f));
                o.z = ttf(fmaxf(fmaf(p2, w2.z, fmaf(p1, w1.z, fmaf(p0, w0.z, bb.z))), 0.f));
                o.w = ttf(fmaxf(fmaf(p2, w2.w, fmaf(p1, w1.w, fmaf(p0, w0.w, bb.w))), 0.f));
                *reinterpret_cast<float4*>(&s.A[row * 68 + c]) = o;
            }
        }
        __syncwarp();

        int wr0 = warp * 16 + (lane >> 2);
        int wr1 = wr0 + 8;
        int si0 = s.si[wr0], di0 = s.di[wr0];
        int si1 = s.si[wr1], di1 = s.di[wr1];

        float acc[8][4];
        #pragma unroll
        for (int n = 0; n < 8; n++) { acc[n][0] = acc[n][1] = acc[n][2] = acc[n][3] = 0.f; }
        gemm16(s.A, s.W2, warp, lane, acc);
        __syncwarp();

        // ---- epi1: delta = relu(.+b2) -> Dl; q = adst-asrc+delta -> A ----
        #pragma unroll
        for (int n = 0; n < 8; n++) {
            int colb = n * 8 + (lane & 3) * 2;
            float2 b2v = *reinterpret_cast<const float2*>(&s.b2[colb]);
            float2 ad0 = *reinterpret_cast<const float2*>(&g_adst[di0 * 64 + colb]);
            float2 as0 = *reinterpret_cast<const float2*>(&g_asrc[si0 * 64 + colb]);
            float d0 = fmaxf(acc[n][0] + b2v.x, 0.f);
            float d1 = fmaxf(acc[n][1] + b2v.y, 0.f);
            *reinterpret_cast<float2*>(&s.Dl[wr0 * 68 + colb]) = make_float2(d0, d1);
            *reinterpret_cast<float2*>(&s.A[wr0 * 68 + colb]) =
                make_float2(ttf(ad0.x - as0.x + d0), ttf(ad0.y - as0.y + d1));
            float2 ad1 = *reinterpret_cast<const float2*>(&g_adst[di1 * 64 + colb]);
            float2 as1 = *reinterpret_cast<const float2*>(&g_asrc[si1 * 64 + colb]);
            float d2 = fmaxf(acc[n][2] + b2v.x, 0.f);
            float d3 = fmaxf(acc[n][3] + b2v.y, 0.f);
            *reinterpret_cast<float2*>(&s.Dl[wr1 * 68 + colb]) = make_float2(d2, d3);
            *reinterpret_cast<float2*>(&s.A[wr1 * 68 + colb]) =
                make_float2(ttf(ad1.x - as1.x + d2), ttf(ad1.y - as1.y + d3));
        }
        __syncwarp();

        #pragma unroll
        for (int n = 0; n < 8; n++) { acc[n][0] = acc[n][1] = acc[n][2] = acc[n][3] = 0.f; }
        gemm16(s.A, s.W3, warp, lane, acc);
        __syncwarp();

        // ---- epi2: t = relu(.+b3) -> A ----
        #pragma unroll
        for (int n = 0; n < 8; n++) {
            int colb = n * 8 + (lane & 3) * 2;
            float2 b3v = *reinterpret_cast<const float2*>(&s.b3[colb]);
            *reinterpret_cast<float2*>(&s.A[wr0 * 68 + colb]) =
                make_float2(ttf(fmaxf(acc[n][0] + b3v.x, 0.f)), ttf(fmaxf(acc[n][1] + b3v.y, 0.f)));
            *reinterpret_cast<float2*>(&s.A[wr1 * 68 + colb]) =
                make_float2(ttf(fmaxf(acc[n][2] + b3v.x, 0.f)), ttf(fmaxf(acc[n][3] + b3v.y, 0.f)));
        }
        __syncwarp();

        #pragma unroll
        for (int n = 0; n < 8; n++) { acc[n][0] = acc[n][1] = acc[n][2] = acc[n][3] = 0.f; }
        gemm16(s.A, s.W4, warp, lane, acc);

        // ---- epi3: p = exp(relu(.+b4)); num = p*(v+delta); vector RED ----
        bool v0 = (tile * 256 + wr0) < ne;
        bool v1 = (tile * 256 + wr1) < ne;
        bool even = ((lane & 1) == 0);
        #pragma unroll
        for (int n = 0; n < 8; n++) {
            int colb = n * 8 + (lane & 3) * 2;
            float2 b4v = *reinterpret_cast<const float2*>(&s.b4[colb]);
            // half 0
            {
                float p0 = fexp(fmaxf(acc[n][0] + b4v.x, 0.f));
                float p1 = fexp(fmaxf(acc[n][1] + b4v.y, 0.f));
                float2 vv = *reinterpret_cast<const float2*>(&g_v[si0 * 64 + colb]);
                float2 dd = *reinterpret_cast<const float2*>(&s.Dl[wr0 * 68 + colb]);
                float num0 = p0 * (vv.x + dd.x);
                float num1 = p1 * (vv.y + dd.y);
                float sa = even ? p0 : num0;
                float sb = even ? p1 : num1;
                float ra = __shfl_xor_sync(0xffffffffu, sa, 1);
                float rb = __shfl_xor_sync(0xffffffffu, sb, 1);
                if (v0) {
                    float* nd = &g_nd[di0 * 128];
                    if (even) red_v4(&nd[colb], num0, num1, ra, rb);
                    else      red_v4(&nd[64 + colb - 2], ra, rb, p0, p1);
                }
            }
            // half 1
            {
                float p0 = fexp(fmaxf(acc[n][2] + b4v.x, 0.f));
                float p1 = fexp(fmaxf(acc[n][3] + b4v.y, 0.f));
                float2 vv = *reinterpret_cast<const float2*>(&g_v[si1 * 64 + colb]);
                float2 dd = *reinterpret_cast<const float2*>(&s.Dl[wr1 * 68 + colb]);
                float num0 = p0 * (vv.x + dd.x);
                float num1 = p1 * (vv.y + dd.y);
                float sa = even ? p0 : num0;
                float sb = even ? p1 : num1;
                float ra = __shfl_xor_sync(0xffffffffu, sa, 1);
                float rb = __shfl_xor_sync(0xffffffffu, sb, 1);
                if (v1) {
                    float* nd = &g_nd[di1 * 128];
                    if (even) red_v4(&nd[colb], num0, num1, ra, rb);
                    else      red_v4(&nd[64 + colb - 2], ra, rb, p0, p1);
                }
            }
        }
    }
}

// ================= out kernel (round-1 version) =================
struct OutSmem {
    float W[4096];
    float b[64];
    float rs[8][64];
};

__global__ __launch_bounds__(256, 3) void out_kernel(
    const float* __restrict__ Wout, const float* __restrict__ bout,
    float* __restrict__ out, int nn)
{
    extern __shared__ char raw[];
    OutSmem& s = *reinterpret_cast<OutSmem*>(raw);
    int tid = threadIdx.x;
    for (int i = tid; i < 4096; i += 256) s.W[i] = Wout[i];
    if (tid < 64) s.b[tid] = bout[tid];
    __syncthreads();

    int warp = tid >> 5, lane = tid & 31, c0 = lane * 2;
    int totW = (gridDim.x * 256) >> 5;
    for (int node = (blockIdx.x * 256 + tid) >> 5; node < nn; node += totW) {
        float2 nm = *reinterpret_cast<float2*>(&g_nd[node * 128 + c0]);
        float2 dn = *reinterpret_cast<float2*>(&g_nd[node * 128 + 64 + c0]);
        float r0 = nm.x / (dn.x + 1e-16f);
        float r1 = nm.y / (dn.y + 1e-16f);
        s.rs[warp][c0] = r0; s.rs[warp][c0 + 1] = r1;
        __syncwarp();
        float o0 = s.b[c0], o1 = s.b[c0 + 1];
        #pragma unroll 16
        for (int k = 0; k < 64; k++) {
            float rk = s.rs[warp][k];
            float2 w = *reinterpret_cast<float2*>(&s.W[k * 64 + c0]);
            o0 = fmaf(rk, w.x, o0); o1 = fmaf(rk, w.y, o1);
        }
        *reinterpret_cast<float2*>(&out[node * 64 + c0]) =
            make_float2(fmaxf(o0, 0.f), fmaxf(o1, 0.f));
        __syncwarp();
    }
}

// ================= launch =================
extern "C" void kernel_launch(void* const* d_in, const int* in_sizes, int n_in,
                              void* d_out, int out_size)
{
    const float* x     = (const float*)d_in[0];
    const float* pos   = (const float*)d_in[1];
    const float* W_in  = (const float*)d_in[2];
    const float* b_in  = (const float*)d_in[3];
    const float* W_src = (const float*)d_in[4];
    const float* W_dst = (const float*)d_in[5];
    const float* W_lin = (const float*)d_in[6];
    const float* b_lin = (const float*)d_in[7];
    const float* Wp1   = (const float*)d_in[8];
    const float* bp1   = (const float*)d_in[9];
    const float* Wp2   = (const float*)d_in[10];
    const float* bp2   = (const float*)d_in[11];
    const float* Wa1   = (const float*)d_in[12];
    const float* ba1   = (const float*)d_in[13];
    const float* Wa2   = (const float*)d_in[14];
    const float* ba2   = (const float*)d_in[15];
    const float* W_out = (const float*)d_in[16];
    const float* b_out = (const float*)d_in[17];
    const int*   ei    = (const int*)d_in[18];
    float* out = (float*)d_out;

    int nn = in_sizes[0] / 64;
    int ne = in_sizes[18] / 2;

    cudaFuncSetAttribute(node_kernel, cudaFuncAttributeMaxDynamicSharedMemorySize, (int)sizeof(NodeSmem));
    cudaFuncSetAttribute(edge_mma_kernel, cudaFuncAttributeMaxDynamicSharedMemorySize, (int)sizeof(ESmem));
    cudaFuncSetAttribute(out_kernel,  cudaFuncAttributeMaxDynamicSharedMemorySize, (int)sizeof(OutSmem));

    node_kernel<<<592, 256, sizeof(NodeSmem)>>>(x, W_in, b_in, W_src, W_dst, W_lin, b_lin, nn);
    edge_mma_kernel<<<148, 512, sizeof(ESmem)>>>(pos, ei, Wp1, bp1, Wp2, bp2, Wa1, ba1, Wa2, ba2, ne);
    out_kernel<<<592, 256, sizeof(OutSmem)>>>(W_out, b_out, out, nn);
}

// round 8
// speedup vs baseline: 2.3017x; 1.3877x over previous
#include <cuda_runtime.h>
#include <cuda_fp16.h>
#include <cstdint>

#define NN_MAX 60000
#define EE_MAX 960000

__device__ float g_asrc[NN_MAX * 64];
__device__ float g_adst[NN_MAX * 64];
__device__ float g_v[NN_MAX * 64];
__device__ float g_nd[NN_MAX * 128];   // [node][0:64]=num, [64:128]=den

// ---------------- helpers ----------------
__device__ __forceinline__ uint32_t pack_h2(float a, float b) {
    __half2 h = __floats2half2_rn(a, b);
    return *reinterpret_cast<uint32_t*>(&h);
}
__device__ __forceinline__ void red_v4(float* p, float a, float b, float c, float d) {
    asm volatile("red.global.add.v4.f32 [%0], {%1,%2,%3,%4};"
                 :: "l"(p), "f"(a), "f"(b), "f"(c), "f"(d) : "memory");
}
// exp(a) for a >= 0 on the FMA pipe (no MUFU)
__device__ __forceinline__ float fexp(float a) {
    float t = a * 1.4426950408889634f;
    float fi = rintf(t);
    float f = t - fi;
    float p = fmaf(f, 1.3333558e-3f, 9.6181291e-3f);
    p = fmaf(p, f, 5.5504109e-2f);
    p = fmaf(p, f, 2.4022651e-1f);
    p = fmaf(p, f, 6.9314718e-1f);
    p = fmaf(p, f, 1.0f);
    return p * __int_as_float(((int)fi + 127) << 23);
}
__device__ __forceinline__ void mma_f16(float* d, uint32_t a0, uint32_t a1,
                                        uint32_t a2, uint32_t a3,
                                        uint32_t b0, uint32_t b1) {
    asm volatile(
        "mma.sync.aligned.m16n8k16.row.col.f32.f16.f16.f32 "
        "{%0,%1,%2,%3}, {%4,%5,%6,%7}, {%8,%9}, {%0,%1,%2,%3};"
        : "+f"(d[0]), "+f"(d[1]), "+f"(d[2]), "+f"(d[3])
        : "r"(a0), "r"(a1), "r"(a2), "r"(a3), "r"(b0), "r"(b1));
}

// ================= node kernel: 2 nodes per warp-iteration =================
struct NodeSmem {
    float Win[4096], Ws[4096], Wd[4096], Wl[4096];
    float bin[64], bl[64];
    float xs[8][2][64];
    float hs[8][2][64];
};

__global__ __launch_bounds__(256, 3) void node_kernel(
    const float* __restrict__ x,
    const float* __restrict__ Win, const float* __restrict__ bin,
    const float* __restrict__ Wsrc, const float* __restrict__ Wdst,
    const float* __restrict__ Wlin, const float* __restrict__ blin, int nn)
{
    extern __shared__ char raw[];
    NodeSmem& s = *reinterpret_cast<NodeSmem*>(raw);
    int tid = threadIdx.x;
    for (int i = tid; i < 4096; i += 256) {
        s.Win[i] = Win[i]; s.Ws[i] = Wsrc[i]; s.Wd[i] = Wdst[i]; s.Wl[i] = Wlin[i];
    }
    if (tid < 64) { s.bin[tid] = bin[tid]; s.bl[tid] = blin[tid]; }
    __syncthreads();

    int warp = tid >> 5, lane = tid & 31, c0 = lane * 2;
    int totW = (gridDim.x * 256) >> 5;
    int npairs = (nn + 1) >> 1;
    for (int pr = (blockIdx.x * 256 + tid) >> 5; pr < npairs; pr += totW) {
        int n0 = pr * 2, n1 = n0 + 1;
        bool has1 = n1 < nn;
        float2 xa = *reinterpret_cast<const float2*>(&x[n0 * 64 + c0]);
        float2 xb = has1 ? *reinterpret_cast<const float2*>(&x[n1 * 64 + c0]) : make_float2(0.f, 0.f);
        s.xs[warp][0][c0] = xa.x; s.xs[warp][0][c0 + 1] = xa.y;
        s.xs[warp][1][c0] = xb.x; s.xs[warp][1][c0 + 1] = xb.y;
        __syncwarp();
        float ha0 = s.bin[c0], ha1 = s.bin[c0 + 1], hb0 = ha0, hb1 = ha1;
        #pragma unroll 8
        for (int k = 0; k < 64; k++) {
            float xka = s.xs[warp][0][k], xkb = s.xs[warp][1][k];
            float2 w = *reinterpret_cast<float2*>(&s.Win[k * 64 + c0]);
            ha0 = fmaf(xka, w.x, ha0); ha1 = fmaf(xka, w.y, ha1);
            hb0 = fmaf(xkb, w.x, hb0); hb1 = fmaf(xkb, w.y, hb1);
        }
        ha0 = fmaxf(ha0, 0.f); ha1 = fmaxf(ha1, 0.f);
        hb0 = fmaxf(hb0, 0.f); hb1 = fmaxf(hb1, 0.f);
        __syncwarp();
        s.hs[warp][0][c0] = ha0; s.hs[warp][0][c0 + 1] = ha1;
        s.hs[warp][1][c0] = hb0; s.hs[warp][1][c0 + 1] = hb1;
        __syncwarp();
        float sa0 = 0.f, sa1 = 0.f, da0 = 0.f, da1 = 0.f;
        float sb0 = 0.f, sb1 = 0.f, db0 = 0.f, db1 = 0.f;
        float va0 = s.bl[c0], va1 = s.bl[c0 + 1], vb0 = va0, vb1 = va1;
        #pragma unroll 4
        for (int k = 0; k < 64; k++) {
            float hka = s.hs[warp][0][k], hkb = s.hs[warp][1][k];
            float2 ws = *reinterpret_cast<float2*>(&s.Ws[k * 64 + c0]);
            float2 wd = *reinterpret_cast<float2*>(&s.Wd[k * 64 + c0]);
            float2 wl = *reinterpret_cast<float2*>(&s.Wl[k * 64 + c0]);
            sa0 = fmaf(hka, ws.x, sa0); sa1 = fmaf(hka, ws.y, sa1);
            da0 = fmaf(hka, wd.x, da0); da1 = fmaf(hka, wd.y, da1);
            va0 = fmaf(hka, wl.x, va0); va1 = fmaf(hka, wl.y, va1);
            sb0 = fmaf(hkb, ws.x, sb0); sb1 = fmaf(hkb, ws.y, sb1);
            db0 = fmaf(hkb, wd.x, db0); db1 = fmaf(hkb, wd.y, db1);
            vb0 = fmaf(hkb, wl.x, vb0); vb1 = fmaf(hkb, wl.y, vb1);
        }
        *reinterpret_cast<float2*>(&g_asrc[n0 * 64 + c0]) = make_float2(sa0, sa1);
        *reinterpret_cast<float2*>(&g_adst[n0 * 64 + c0]) = make_float2(da0, da1);
        *reinterpret_cast<float2*>(&g_v[n0 * 64 + c0])    = make_float2(va0, va1);
        *reinterpret_cast<float4*>(&g_nd[n0 * 128 + lane * 4]) = make_float4(0.f, 0.f, 0.f, 0.f);
        if (has1) {
            *reinterpret_cast<float2*>(&g_asrc[n1 * 64 + c0]) = make_float2(sb0, sb1);
            *reinterpret_cast<float2*>(&g_adst[n1 * 64 + c0]) = make_float2(db0, db1);
            *reinterpret_cast<float2*>(&g_v[n1 * 64 + c0])    = make_float2(vb0, vb1);
            *reinterpret_cast<float4*>(&g_nd[n1 * 128 + lane * 4]) = make_float4(0.f, 0.f, 0.f, 0.f);
        }
        __syncwarp();
    }
}

// ================= edge kernel: mma.sync f16, 128-edge tiles, 2 CTAs/SM =================
// A: 128 rows x 64 cols f16, row stride 36 half2 (72 halves). Weights [n][k] f16,
// n stride 36 half2. Dl fp32 [128][68].
struct ESmem {
    uint32_t W2h[64 * 36], W3h[64 * 36], W4h[64 * 36];
    uint32_t Ah[128 * 36];
    float Dl[128 * 68];
    float Wp1[192], b1[64], b2[64], b3[64], b4[64];
    float px[128], py[128], pz[128];
    int si[128], di[128];
};

__device__ __forceinline__ void gemm16h(const uint32_t* __restrict__ Ah,
                                        const uint32_t* __restrict__ Wh,
                                        int warp, int lane, float acc[8][4]) {
    int r0 = warp * 16 + (lane >> 2);
    int a0i = r0 * 36 + (lane & 3);
    int a1i = (r0 + 8) * 36 + (lane & 3);
    #pragma unroll
    for (int k16 = 0; k16 < 4; k16++) {
        uint32_t a0 = Ah[a0i + k16 * 8];
        uint32_t a1 = Ah[a1i + k16 * 8];
        uint32_t a2 = Ah[a0i + k16 * 8 + 4];
        uint32_t a3 = Ah[a1i + k16 * 8 + 4];
        int bb = (lane >> 2) * 36 + (lane & 3) + k16 * 8;
        #pragma unroll
        for (int n = 0; n < 8; n++) {
            mma_f16(acc[n], a0, a1, a2, a3, Wh[bb + n * 288], Wh[bb + n * 288 + 4]);
        }
    }
}

__global__ __launch_bounds__(256, 2) void edge_mma_kernel(
    const float* __restrict__ pos, const int* __restrict__ ei,
    const float* __restrict__ Wp1, const float* __restrict__ bp1,
    const float* __restrict__ Wp2, const float* __restrict__ bp2,
    const float* __restrict__ Wa1, const float* __restrict__ ba1,
    const float* __restrict__ Wa2, const float* __restrict__ ba2, int ne)
{
    extern __shared__ char raw[];
    ESmem& s = *reinterpret_cast<ESmem*>(raw);
    int tid = threadIdx.x;

    // weights: fp32 [k][n] -> f16 pairs [n][k/2]
    for (int i = tid; i < 2048; i += 256) {
        int n = i >> 5, k2 = i & 31;
        s.W2h[n * 36 + k2] = pack_h2(Wp2[(2 * k2) * 64 + n], Wp2[(2 * k2 + 1) * 64 + n]);
        s.W3h[n * 36 + k2] = pack_h2(Wa1[(2 * k2) * 64 + n], Wa1[(2 * k2 + 1) * 64 + n]);
        s.W4h[n * 36 + k2] = pack_h2(Wa2[(2 * k2) * 64 + n], Wa2[(2 * k2 + 1) * 64 + n]);
    }
    if (tid < 192) s.Wp1[tid] = Wp1[tid];
    if (tid < 64) { s.b1[tid] = bp1[tid]; s.b2[tid] = bp2[tid]; s.b3[tid] = ba1[tid]; s.b4[tid] = ba2[tid]; }
    __syncthreads();

    int warp = tid >> 5, lane = tid & 31;
    int ntiles = (ne + 127) / 128;

    for (int tile = blockIdx.x; tile < ntiles; tile += gridDim.x) {
        __syncthreads();
        if (tid < 128) {
            int ed = tile * 128 + tid;
            int si = 0, di = 0;
            float p0 = 0.f, p1 = 0.f, p2 = 0.f;
            if (ed < ne) {
                si = ei[ed]; di = ei[ne + ed];
                p0 = pos[di * 3 + 0] - pos[si * 3 + 0];
                p1 = pos[di * 3 + 1] - pos[si * 3 + 1];
                p2 = pos[di * 3 + 2] - pos[si * 3 + 2];
            }
            s.si[tid] = si; s.di[tid] = di;
            s.px[tid] = p0; s.py[tid] = p1; s.pz[tid] = p2;
        }
        __syncthreads();

        // ---- stage0: h1 = relu(pd @ Wp1 + b1) -> A (f16) ----
        {
            int row = warp * 16 + (lane >> 1);
            int ch = (lane & 1) * 32;
            float p0 = s.px[row], p1 = s.py[row], p2 = s.pz[row];
            #pragma unroll
            for (int j = 0; j < 8; j++) {
                int c = ch + j * 4;
                float4 w0 = *reinterpret_cast<const float4*>(&s.Wp1[c]);
                float4 w1 = *reinterpret_cast<const float4*>(&s.Wp1[64 + c]);
                float4 w2 = *reinterpret_cast<const float4*>(&s.Wp1[128 + c]);
                float4 bb = *reinterpret_cast<const float4*>(&s.b1[c]);
                float ox = fmaxf(fmaf(p2, w2.x, fmaf(p1, w1.x, fmaf(p0, w0.x, bb.x))), 0.f);
                float oy = fmaxf(fmaf(p2, w2.y, fmaf(p1, w1.y, fmaf(p0, w0.y, bb.y))), 0.f);
                float oz = fmaxf(fmaf(p2, w2.z, fmaf(p1, w1.z, fmaf(p0, w0.z, bb.z))), 0.f);
                float ow = fmaxf(fmaf(p2, w2.w, fmaf(p1, w1.w, fmaf(p0, w0.w, bb.w))), 0.f);
                s.Ah[row * 36 + c / 2]     = pack_h2(ox, oy);
                s.Ah[row * 36 + c / 2 + 1] = pack_h2(oz, ow);
            }
        }
        __syncwarp();

        int wr0 = warp * 16 + (lane >> 2);
        int wr1 = wr0 + 8;
        int si0 = s.si[wr0], di0 = s.di[wr0];
        int si1 = s.si[wr1], di1 = s.di[wr1];

        float acc[8][4];
        #pragma unroll
        for (int n = 0; n < 8; n++) { acc[n][0] = acc[n][1] = acc[n][2] = acc[n][3] = 0.f; }
        gemm16h(s.Ah, s.W2h, warp, lane, acc);
        __syncwarp();

        // ---- epi1: delta = relu(.+b2) -> Dl; q = adst-asrc+delta -> A ----
        #pragma unroll
        for (int n = 0; n < 8; n++) {
            int colb = n * 8 + (lane & 3) * 2;
            float2 b2v = *reinterpret_cast<const float2*>(&s.b2[colb]);
            float2 ad0 = *reinterpret_cast<const float2*>(&g_adst[di0 * 64 + colb]);
            float2 as0 = *reinterpret_cast<const float2*>(&g_asrc[si0 * 64 + colb]);
            float d0 = fmaxf(acc[n][0] + b2v.x, 0.f);
            float d1 = fmaxf(acc[n][1] + b2v.y, 0.f);
            *reinterpret_cast<float2*>(&s.Dl[wr0 * 68 + colb]) = make_float2(d0, d1);
            s.Ah[wr0 * 36 + colb / 2] = pack_h2(ad0.x - as0.x + d0, ad0.y - as0.y + d1);
            float2 ad1 = *reinterpret_cast<const float2*>(&g_adst[di1 * 64 + colb]);
            float2 as1 = *reinterpret_cast<const float2*>(&g_asrc[si1 * 64 + colb]);
            float d2 = fmaxf(acc[n][2] + b2v.x, 0.f);
            float d3 = fmaxf(acc[n][3] + b2v.y, 0.f);
            *reinterpret_cast<float2*>(&s.Dl[wr1 * 68 + colb]) = make_float2(d2, d3);
            s.Ah[wr1 * 36 + colb / 2] = pack_h2(ad1.x - as1.x + d2, ad1.y - as1.y + d3);
        }
        __syncwarp();

        #pragma unroll
        for (int n = 0; n < 8; n++) { acc[n][0] = acc[n][1] = acc[n][2] = acc[n][3] = 0.f; }
        gemm16h(s.Ah, s.W3h, warp, lane, acc);
        __syncwarp();

        // ---- epi2: t = relu(.+b3) -> A ----
        #pragma unroll
        for (int n = 0; n < 8; n++) {
            int colb = n * 8 + (lane & 3) * 2;
            float2 b3v = *reinterpret_cast<const float2*>(&s.b3[colb]);
            s.Ah[wr0 * 36 + colb / 2] =
                pack_h2(fmaxf(acc[n][0] + b3v.x, 0.f), fmaxf(acc[n][1] + b3v.y, 0.f));
            s.Ah[wr1 * 36 + colb / 2] =
                pack_h2(fmaxf(acc[n][2] + b3v.x, 0.f), fmaxf(acc[n][3] + b3v.y, 0.f));
        }
        __syncwarp();

        #pragma unroll
        for (int n = 0; n < 8; n++) { acc[n][0] = acc[n][1] = acc[n][2] = acc[n][3] = 0.f; }
        gemm16h(s.Ah, s.W4h, warp, lane, acc);

        // ---- epi3: p = exp(relu(.+b4)); num = p*(v+delta); vector RED ----
        bool v0 = (tile * 128 + wr0) < ne;
        bool v1 = (tile * 128 + wr1) < ne;
        bool even = ((lane & 1) == 0);
        #pragma unroll
        for (int n = 0; n < 8; n++) {
            int colb = n * 8 + (lane & 3) * 2;
            float2 b4v = *reinterpret_cast<const float2*>(&s.b4[colb]);
            {
                float p0 = fexp(fmaxf(acc[n][0] + b4v.x, 0.f));
                float p1 = fexp(fmaxf(acc[n][1] + b4v.y, 0.f));
                float2 vv = *reinterpret_cast<const float2*>(&g_v[si0 * 64 + colb]);
                float2 dd = *reinterpret_cast<const float2*>(&s.Dl[wr0 * 68 + colb]);
                float num0 = p0 * (vv.x + dd.x);
                float num1 = p1 * (vv.y + dd.y);
                float sa = even ? p0 : num0;
                float sb = even ? p1 : num1;
                float ra = __shfl_xor_sync(0xffffffffu, sa, 1);
                float rb = __shfl_xor_sync(0xffffffffu, sb, 1);
                if (v0) {
                    float* nd = &g_nd[di0 * 128];
                    if (even) red_v4(&nd[colb], num0, num1, ra, rb);
                    else      red_v4(&nd[64 + colb - 2], ra, rb, p0, p1);
                }
            }
            {
                float p0 = fexp(fmaxf(acc[n][2] + b4v.x, 0.f));
                float p1 = fexp(fmaxf(acc[n][3] + b4v.y, 0.f));
                float2 vv = *reinterpret_cast<const float2*>(&g_v[si1 * 64 + colb]);
                float2 dd = *reinterpret_cast<const float2*>(&s.Dl[wr1 * 68 + colb]);
                float num0 = p0 * (vv.x + dd.x);
                float num1 = p1 * (vv.y + dd.y);
                float sa = even ? p0 : num0;
                float sb = even ? p1 : num1;
                float ra = __shfl_xor_sync(0xffffffffu, sa, 1);
                float rb = __shfl_xor_sync(0xffffffffu, sb, 1);
                if (v1) {
                    float* nd = &g_nd[di1 * 128];
                    if (even) red_v4(&nd[colb], num0, num1, ra, rb);
                    else      red_v4(&nd[64 + colb - 2], ra, rb, p0, p1);
                }
            }
        }
    }
}

// ================= out kernel =================
struct OutSmem {
    float W[4096];
    float b[64];
    float rs[8][64];
};

__global__ __launch_bounds__(256, 3) void out_kernel(
    const float* __restrict__ Wout, const float* __restrict__ bout,
    float* __restrict__ out, int nn)
{
    extern __shared__ char raw[];
    OutSmem& s = *reinterpret_cast<OutSmem*>(raw);
    int tid = threadIdx.x;
    for (int i = tid; i < 4096; i += 256) s.W[i] = Wout[i];
    if (tid < 64) s.b[tid] = bout[tid];
    __syncthreads();

    int warp = tid >> 5, lane = tid & 31, c0 = lane * 2;
    int totW = (gridDim.x * 256) >> 5;
    for (int node = (blockIdx.x * 256 + tid) >> 5; node < nn; node += totW) {
        float2 nm = *reinterpret_cast<float2*>(&g_nd[node * 128 + c0]);
        float2 dn = *reinterpret_cast<float2*>(&g_nd[node * 128 + 64 + c0]);
        float r0 = nm.x / (dn.x + 1e-16f);
        float r1 = nm.y / (dn.y + 1e-16f);
        s.rs[warp][c0] = r0; s.rs[warp][c0 + 1] = r1;
        __syncwarp();
        float o0 = s.b[c0], o1 = s.b[c0 + 1];
        #pragma unroll 16
        for (int k = 0; k < 64; k++) {
            float rk = s.rs[warp][k];
            float2 w = *reinterpret_cast<float2*>(&s.W[k * 64 + c0]);
            o0 = fmaf(rk, w.x, o0); o1 = fmaf(rk, w.y, o1);
        }
        *reinterpret_cast<float2*>(&out[node * 64 + c0]) =
            make_float2(fmaxf(o0, 0.f), fmaxf(o1, 0.f));
        __syncwarp();
    }
}

// ================= launch =================
extern "C" void kernel_launch(void* const* d_in, const int* in_sizes, int n_in,
                              void* d_out, int out_size)
{
    const float* x     = (const float*)d_in[0];
    const float* pos   = (const float*)d_in[1];
    const float* W_in  = (const float*)d_in[2];
    const float* b_in  = (const float*)d_in[3];
    const float* W_src = (const float*)d_in[4];
    const float* W_dst = (const float*)d_in[5];
    const float* W_lin = (const float*)d_in[6];
    const float* b_lin = (const float*)d_in[7];
    const float* Wp1   = (const float*)d_in[8];
    const float* bp1   = (const float*)d_in[9];
    const float* Wp2   = (const float*)d_in[10];
    const float* bp2   = (const float*)d_in[11];
    const float* Wa1   = (const float*)d_in[12];
    const float* ba1   = (const float*)d_in[13];
    const float* Wa2   = (const float*)d_in[14];
    const float* ba2   = (const float*)d_in[15];
    const float* W_out = (const float*)d_in[16];
    const float* b_out = (const float*)d_in[17];
    const int*   ei    = (const int*)d_in[18];
    float* out = (float*)d_out;

    int nn = in_sizes[0] / 64;
    int ne = in_sizes[18] / 2;

    cudaFuncSetAttribute(node_kernel, cudaFuncAttributeMaxDynamicSharedMemorySize, (int)sizeof(NodeSmem));
    cudaFuncSetAttribute(edge_mma_kernel, cudaFuncAttributeMaxDynamicSharedMemorySize, (int)sizeof(ESmem));
    cudaFuncSetAttribute(out_kernel,  cudaFuncAttributeMaxDynamicSharedMemorySize, (int)sizeof(OutSmem));

    node_kernel<<<592, 256, sizeof(NodeSmem)>>>(x, W_in, b_in, W_src, W_dst, W_lin, b_lin, nn);
    edge_mma_kernel<<<296, 256, sizeof(ESmem)>>>(pos, ei, Wp1, bp1, Wp2, bp2, Wa1, ba1, Wa2, ba2, ne);
    out_kernel<<<592, 256, sizeof(OutSmem)>>>(W_out, b_out, out, nn);
}